// round 10
// baseline (speedup 1.0000x reference)
#include <cuda_runtime.h>
#include <cuda_bf16.h>

#define SEQ    256
#define BATCH  32
#define IDIM   256
#define HDIM   512
#define VOCABN 10000
#define SB     (SEQ*BATCH)      /* 8192 */
#define CHUNK  32
#define NCHUNK (SEQ/CHUNK)      /* 8 */
#define MC     (CHUNK*BATCH)    /* 1024 */

#define KSTR   72               /* padded smem row stride (bf16 elems), 144B */
#define A_EL   (128*KSTR)
#define B_EL   (64*KSTR)
#define STAGE_EL (2*A_EL + 2*B_EL)
#define SMEM_BYTES (2*STAGE_EL*2)        /* 110592 */

typedef unsigned int u32;

// ---------------- static device scratch ----------------
__device__ float         g_T0[(size_t)MC * HDIM * HDIM];     // 1 GiB, chunk parity 0
__device__ float         g_T1[(size_t)MC * HDIM * HDIM];     // 1 GiB, chunk parity 1
__device__ __nv_bfloat16 g_Ah[(size_t)HDIM * IDIM * HDIM];
__device__ __nv_bfloat16 g_Al[(size_t)HDIM * IDIM * HDIM];
__device__ __nv_bfloat16 g_Wh[(size_t)VOCABN * HDIM];
__device__ __nv_bfloat16 g_Wl[(size_t)VOCABN * HDIM];
__device__ __nv_bfloat16 g_Uh[(size_t)HDIM * IDIM];
__device__ __nv_bfloat16 g_Ul[(size_t)HDIM * IDIM];
__device__ __nv_bfloat16 g_Xh[(size_t)SB * IDIM];
__device__ __nv_bfloat16 g_Xl[(size_t)SB * IDIM];
__device__ __nv_bfloat16 g_Hh[(size_t)SB * HDIM];
__device__ __nv_bfloat16 g_Hl[(size_t)SB * HDIM];
__device__ float         g_P [(size_t)SB * HDIM];
__device__ int           g_cnt[CHUNK * BATCH];

// ---------------- ptx helpers ----------------
__device__ __forceinline__ void mma16816(float c[4], const u32 a[4], const u32 b[2]) {
    asm volatile(
        "mma.sync.aligned.m16n8k16.row.col.f32.bf16.bf16.f32 "
        "{%0,%1,%2,%3}, {%4,%5,%6,%7}, {%8,%9}, {%0,%1,%2,%3};\n"
        : "+f"(c[0]), "+f"(c[1]), "+f"(c[2]), "+f"(c[3])
        : "r"(a[0]), "r"(a[1]), "r"(a[2]), "r"(a[3]), "r"(b[0]), "r"(b[1]));
}
__device__ __forceinline__ u32 smem_u32(const void* p) {
    return (u32)__cvta_generic_to_shared(p);
}
__device__ __forceinline__ void cpa16(u32 dst, const void* src, int sz) {
    asm volatile("cp.async.cg.shared.global [%0], [%1], 16, %2;\n"
                 :: "r"(dst), "l"(src), "r"(sz));
}
__device__ __forceinline__ void cpcommit() { asm volatile("cp.async.commit_group;\n"); }
template<int N> __device__ __forceinline__ void cpwait() {
    asm volatile("cp.async.wait_group %0;\n" :: "n"(N));
}
__device__ __forceinline__ void ldsm4(u32& r0, u32& r1, u32& r2, u32& r3, u32 a) {
    asm volatile("ldmatrix.sync.aligned.m8n8.x4.shared.b16 {%0,%1,%2,%3}, [%4];\n"
                 : "=r"(r0), "=r"(r1), "=r"(r2), "=r"(r3) : "r"(a));
}
__device__ __forceinline__ void ldsm4t(u32& r0, u32& r1, u32& r2, u32& r3, u32 a) {
    asm volatile("ldmatrix.sync.aligned.m8n8.x4.trans.shared.b16 {%0,%1,%2,%3}, [%4];\n"
                 : "=r"(r0), "=r"(r1), "=r"(r2), "=r"(r3) : "r"(a));
}

// ---------------- split / embed ----------------
struct __align__(8) Bf4 { __nv_bfloat16 a, b, c, d; };

__global__ void split_kernel(const float4* __restrict__ src,
                             Bf4* __restrict__ hi, Bf4* __restrict__ lo, int n4) {
    int i = blockIdx.x * blockDim.x + threadIdx.x;
    if (i >= n4) return;
    float4 v = src[i];
    Bf4 h, l;
    h.a = __float2bfloat16(v.x); l.a = __float2bfloat16(v.x - __bfloat162float(h.a));
    h.b = __float2bfloat16(v.y); l.b = __float2bfloat16(v.y - __bfloat162float(h.b));
    h.c = __float2bfloat16(v.z); l.c = __float2bfloat16(v.z - __bfloat162float(h.c));
    h.d = __float2bfloat16(v.w); l.d = __float2bfloat16(v.w - __bfloat162float(h.d));
    hi[i] = h; lo[i] = l;
}

__global__ void embed_kernel(const int* __restrict__ tok, const float* __restrict__ E,
                             __nv_bfloat16* __restrict__ Xh, __nv_bfloat16* __restrict__ Xl) {
    int sb = blockIdx.x;
    int i  = threadIdx.x;
    float v = E[(size_t)tok[sb] * IDIM + i];
    __nv_bfloat16 h = __float2bfloat16(v);
    Xh[(size_t)sb * IDIM + i] = h;
    Xl[(size_t)sb * IDIM + i] = __float2bfloat16(v - __bfloat162float(h));
}

__global__ void zero_cnt_kernel() {
    int i = blockIdx.x * blockDim.x + threadIdx.x;
    if (i < CHUNK * BATCH) g_cnt[i] = 0;
}

// =======================================================================
// T GEMM (pipelined): T[mloc][j][n] = sum_i X[m][i]*A[j][i*H+n] + V[j][n]
// BM=128 BN=64 BK=64, 2-stage cp.async, ldmatrix(.trans).
// MMA inner loop is PASS-MAJOR: consecutive HMMAs hit different accumulators
// (RAW distance 8) instead of the dependent hh/hl/lh triple.
// =======================================================================
__global__ __launch_bounds__(256) void gemm_T2(
    const float* __restrict__ Vw, float* __restrict__ T, int chunk)
{
    extern __shared__ __nv_bfloat16 sm[];
    const int tid = threadIdx.x, lane = tid & 31, w = tid >> 5;
    const int grp = lane >> 2, qp2 = (lane & 3) * 2;
    const int wm0 = (w & 3) * 32, wn0 = (w >> 2) * 32;
    const int j = blockIdx.z, mBase = blockIdx.x * 128, nBase = blockIdx.y * 64;
    const int mG = chunk * MC + mBase;

    float acc[2][4][4];
#pragma unroll
    for (int a = 0; a < 2; a++)
#pragma unroll
        for (int b = 0; b < 4; b++)
#pragma unroll
            for (int c = 0; c < 4; c++) acc[a][b][c] = 0.f;

#define PREFETCH_T(kc_) do {                                                   \
    int st_ = (kc_) & 1;                                                       \
    int kB_ = (kc_) * 64;                                                      \
    __nv_bfloat16* Ah_ = sm + st_ * STAGE_EL;                                  \
    __nv_bfloat16* Al_ = Ah_ + A_EL;                                           \
    __nv_bfloat16* Bh_ = Ah_ + 2 * A_EL;                                       \
    __nv_bfloat16* Bl_ = Bh_ + B_EL;                                           \
    _Pragma("unroll")                                                          \
    for (int q = 0; q < 4; q++) {                                              \
        int id = q * 256 + tid;                                                \
        int row = id >> 3, ks = (id & 7) * 8;                                  \
        size_t g = (size_t)(mG + row) * IDIM + kB_ + ks;                       \
        cpa16(smem_u32(Ah_ + row * KSTR + ks), g_Xh + g, 16);                  \
        cpa16(smem_u32(Al_ + row * KSTR + ks), g_Xl + g, 16);                  \
    }                                                                          \
    _Pragma("unroll")                                                          \
    for (int q = 0; q < 2; q++) {                                              \
        int id = q * 256 + tid;                                                \
        int kr = id >> 3, ns = (id & 7) * 8;                                   \
        size_t g = ((size_t)j * IDIM + kB_ + kr) * HDIM + nBase + ns;          \
        cpa16(smem_u32(Bh_ + kr * KSTR + ns), g_Ah + g, 16);                   \
        cpa16(smem_u32(Bl_ + kr * KSTR + ns), g_Al + g, 16);                   \
    } } while (0)

    PREFETCH_T(0); cpcommit();

    const int r8 = lane & 7, kh = (lane >> 3) & 1, nh = lane >> 4;

    for (int kc = 0; kc < 4; kc++) {
        if (kc < 3) { PREFETCH_T(kc + 1); cpcommit(); cpwait<1>(); }
        else        { cpwait<0>(); }
        __syncthreads();
        int st = kc & 1;
        __nv_bfloat16* Ah_ = sm + st * STAGE_EL;
        u32 aAdH = smem_u32(Ah_ + (wm0 + (lane & 15)) * KSTR + (lane >> 4) * 8);
        u32 aAdL = aAdH + A_EL * 2;
        u32 bAdH = smem_u32(Ah_ + 2 * A_EL + (kh * 8 + r8) * KSTR + wn0 + nh * 8);
        u32 bAdL = bAdH + B_EL * 2;
#pragma unroll
        for (int ks = 0; ks < 4; ks++) {
            u32 aH[2][4], aL[2][4], bH[4][2], bL[4][2];
            ldsm4(aH[0][0], aH[0][1], aH[0][2], aH[0][3], aAdH + ks * 32);
            ldsm4(aH[1][0], aH[1][1], aH[1][2], aH[1][3], aAdH + 2304 + ks * 32);
            ldsm4(aL[0][0], aL[0][1], aL[0][2], aL[0][3], aAdL + ks * 32);
            ldsm4(aL[1][0], aL[1][1], aL[1][2], aL[1][3], aAdL + 2304 + ks * 32);
            ldsm4t(bH[0][0], bH[0][1], bH[1][0], bH[1][1], bAdH + ks * 2304);
            ldsm4t(bH[2][0], bH[2][1], bH[3][0], bH[3][1], bAdH + 32 + ks * 2304);
            ldsm4t(bL[0][0], bL[0][1], bL[1][0], bL[1][1], bAdL + ks * 2304);
            ldsm4t(bL[2][0], bL[2][1], bL[3][0], bL[3][1], bAdL + 32 + ks * 2304);
            // pass-major: 8 independent HMMAs per pass; per-acc order is
            // still hh -> hl -> lh (bit-identical accumulation).
#pragma unroll
            for (int mt = 0; mt < 2; mt++)
#pragma unroll
                for (int nt = 0; nt < 4; nt++)
                    mma16816(acc[mt][nt], aH[mt], bH[nt]);
#pragma unroll
            for (int mt = 0; mt < 2; mt++)
#pragma unroll
                for (int nt = 0; nt < 4; nt++)
                    mma16816(acc[mt][nt], aH[mt], bL[nt]);
#pragma unroll
            for (int mt = 0; mt < 2; mt++)
#pragma unroll
                for (int nt = 0; nt < 4; nt++)
                    mma16816(acc[mt][nt], aL[mt], bH[nt]);
        }
        __syncthreads();
    }
#undef PREFETCH_T

#pragma unroll
    for (int mt = 0; mt < 2; mt++)
#pragma unroll
        for (int nt = 0; nt < 4; nt++) {
            int r  = mBase + wm0 + mt * 16 + grp;
            int cc = nBase + wn0 + nt * 8 + qp2;
            float2 v2 = *(const float2*)&Vw[(size_t)j * HDIM + cc];
            size_t base = ((size_t)r * HDIM + j) * HDIM + cc;
            *(float2*)&T[base] = make_float2(acc[mt][nt][0] + v2.x, acc[mt][nt][1] + v2.y);
            *(float2*)&T[base + (size_t)8 * HDIM * HDIM] =
                make_float2(acc[mt][nt][2] + v2.x, acc[mt][nt][3] + v2.y);
        }
}

// =======================================================================
// TN GEMM (pipelined): C[m][n] = sum_k A[m][k]*B[n][k] + bias[n]
// Same pass-major MMA ordering.
// =======================================================================
__global__ __launch_bounds__(256) void gemm_tn2(
    const __nv_bfloat16* __restrict__ Ahp, const __nv_bfloat16* __restrict__ Alp,
    const __nv_bfloat16* __restrict__ Bhp, const __nv_bfloat16* __restrict__ Blp,
    const float* __restrict__ bias, float* __restrict__ C, int N, int K)
{
    extern __shared__ __nv_bfloat16 sm[];
    const int tid = threadIdx.x, lane = tid & 31, w = tid >> 5;
    const int grp = lane >> 2, qp2 = (lane & 3) * 2;
    const int wm0 = (w & 3) * 32, wn0 = (w >> 2) * 32;
    const int mBase = blockIdx.x * 128, nBase = blockIdx.y * 64;
    const int KC = K >> 6;

    float acc[2][4][4];
#pragma unroll
    for (int a = 0; a < 2; a++)
#pragma unroll
        for (int b = 0; b < 4; b++)
#pragma unroll
            for (int c = 0; c < 4; c++) acc[a][b][c] = 0.f;

#define PREFETCH_N(kc_) do {                                                   \
    int st_ = (kc_) & 1;                                                       \
    int kB_ = (kc_) * 64;                                                      \
    __nv_bfloat16* Ah_ = sm + st_ * STAGE_EL;                                  \
    __nv_bfloat16* Al_ = Ah_ + A_EL;                                           \
    __nv_bfloat16* Bh_ = Ah_ + 2 * A_EL;                                       \
    __nv_bfloat16* Bl_ = Bh_ + B_EL;                                           \
    _Pragma("unroll")                                                          \
    for (int q = 0; q < 4; q++) {                                              \
        int id = q * 256 + tid;                                                \
        int row = id >> 3, ks = (id & 7) * 8;                                  \
        size_t g = (size_t)(mBase + row) * K + kB_ + ks;                       \
        cpa16(smem_u32(Ah_ + row * KSTR + ks), Ahp + g, 16);                   \
        cpa16(smem_u32(Al_ + row * KSTR + ks), Alp + g, 16);                   \
    }                                                                          \
    _Pragma("unroll")                                                          \
    for (int q = 0; q < 2; q++) {                                              \
        int id = q * 256 + tid;                                                \
        int nr = id >> 3, ks = (id & 7) * 8;                                   \
        int gn = nBase + nr;                                                   \
        int ok = gn < N;                                                       \
        int gc = ok ? gn : (N - 1);                                            \
        size_t g = (size_t)gc * K + kB_ + ks;                                  \
        cpa16(smem_u32(Bh_ + nr * KSTR + ks), Bhp + g, ok ? 16 : 0);           \
        cpa16(smem_u32(Bl_ + nr * KSTR + ks), Blp + g, ok ? 16 : 0);           \
    } } while (0)

    PREFETCH_N(0); cpcommit();

    const int r8 = lane & 7, kh = (lane >> 3) & 1, nh = lane >> 4;

    for (int kc = 0; kc < KC; kc++) {
        if (kc < KC - 1) { PREFETCH_N(kc + 1); cpcommit(); cpwait<1>(); }
        else             { cpwait<0>(); }
        __syncthreads();
        int st = kc & 1;
        __nv_bfloat16* Ah_ = sm + st * STAGE_EL;
        u32 aAdH = smem_u32(Ah_ + (wm0 + (lane & 15)) * KSTR + (lane >> 4) * 8);
        u32 aAdL = aAdH + A_EL * 2;
        u32 bAdH = smem_u32(Ah_ + 2 * A_EL + (wn0 + nh * 8 + r8) * KSTR + kh * 8);
        u32 bAdL = bAdH + B_EL * 2;
#pragma unroll
        for (int ks = 0; ks < 4; ks++) {
            u32 aH[2][4], aL[2][4], bH[4][2], bL[4][2];
            ldsm4(aH[0][0], aH[0][1], aH[0][2], aH[0][3], aAdH + ks * 32);
            ldsm4(aH[1][0], aH[1][1], aH[1][2], aH[1][3], aAdH + 2304 + ks * 32);
            ldsm4(aL[0][0], aL[0][1], aL[0][2], aL[0][3], aAdL + ks * 32);
            ldsm4(aL[1][0], aL[1][1], aL[1][2], aL[1][3], aAdL + 2304 + ks * 32);
            ldsm4(bH[0][0], bH[0][1], bH[1][0], bH[1][1], bAdH + ks * 32);
            ldsm4(bH[2][0], bH[2][1], bH[3][0], bH[3][1], bAdH + 2304 + ks * 32);
            ldsm4(bL[0][0], bL[0][1], bL[1][0], bL[1][1], bAdL + ks * 32);
            ldsm4(bL[2][0], bL[2][1], bL[3][0], bL[3][1], bAdL + 2304 + ks * 32);
#pragma unroll
            for (int mt = 0; mt < 2; mt++)
#pragma unroll
                for (int nt = 0; nt < 4; nt++)
                    mma16816(acc[mt][nt], aH[mt], bH[nt]);
#pragma unroll
            for (int mt = 0; mt < 2; mt++)
#pragma unroll
                for (int nt = 0; nt < 4; nt++)
                    mma16816(acc[mt][nt], aH[mt], bL[nt]);
#pragma unroll
            for (int mt = 0; mt < 2; mt++)
#pragma unroll
                for (int nt = 0; nt < 4; nt++)
                    mma16816(acc[mt][nt], aL[mt], bH[nt]);
        }
        __syncthreads();
    }
#undef PREFETCH_N

#pragma unroll
    for (int mt = 0; mt < 2; mt++)
#pragma unroll
        for (int nt = 0; nt < 4; nt++) {
            int r0 = mBase + wm0 + mt * 16 + grp;
            int cc = nBase + wn0 + nt * 8 + qp2;
            if (cc < N) {
                float b0 = bias[cc], b1 = bias[cc + 1];
                *(float2*)&C[(size_t)r0 * N + cc] =
                    make_float2(acc[mt][nt][0] + b0, acc[mt][nt][1] + b1);
                *(float2*)&C[(size_t)(r0 + 8) * N + cc] =
                    make_float2(acc[mt][nt][2] + b0, acc[mt][nt][3] + b1);
            }
        }
}

// =======================================================================
// Fused recurrence for one chunk (R7-proven): 32 steps in one kernel.
// grid 128 = 32 batches x 4 j-quarters; sibling sync via atomic counters.
// =======================================================================
__global__ __launch_bounds__(256) void recur_chunk(
    const float* __restrict__ T, int chunk,
    float* __restrict__ Hfull,
    __nv_bfloat16* __restrict__ Hh, __nv_bfloat16* __restrict__ Hl)
{
    const int tid = threadIdx.x, lane = tid & 31, w = tid >> 5;
    const int bb = blockIdx.x >> 2, jt = blockIdx.x & 3;
    __shared__ float hs[HDIM];

    for (int t = 0; t < CHUNK; t++) {
        const int s = chunk * CHUNK + t;
        if (t > 0) {
            if (tid == 0) {
                while (atomicAdd(&g_cnt[(t - 1) * BATCH + bb], 0) < 4) __nanosleep(32);
            }
            __syncthreads();
        }
        if (s > 0) {
            const float* hp = Hfull + ((size_t)(s - 1) * BATCH + bb) * HDIM;
            for (int k = tid; k < HDIM; k += 256) hs[k] = hp[k];
        } else {
            for (int k = tid; k < HDIM; k += 256) hs[k] = 0.f;
        }
        __syncthreads();

        const int mloc = t * BATCH + bb;
        const int m    = s * BATCH + bb;
#pragma unroll 4
        for (int jj = 0; jj < 16; jj++) {
            int j = jt * 128 + w * 16 + jj;
            const float4* row = (const float4*)(T + ((size_t)mloc * HDIM + j) * HDIM);
            float a = 0.f;
#pragma unroll
            for (int q = 0; q < 4; q++) {
                float4 v = row[lane + q * 32];
                int k = (lane + q * 32) * 4;
                a += v.x * hs[k] + v.y * hs[k+1] + v.z * hs[k+2] + v.w * hs[k+3];
            }
#pragma unroll
            for (int off = 16; off; off >>= 1) a += __shfl_xor_sync(~0u, a, off);
            if (lane == 0) {
                float pre = a + g_P[(size_t)m * HDIM + j];
                float h = pre > 0.f ? pre : 0.f;
                Hfull[(size_t)m * HDIM + j] = h;
                __nv_bfloat16 hh = __float2bfloat16(h);
                Hh[(size_t)m * HDIM + j] = hh;
                Hl[(size_t)m * HDIM + j] = __float2bfloat16(h - __bfloat162float(hh));
            }
        }
        __threadfence();
        __syncthreads();
        if (tid == 0) atomicAdd(&g_cnt[t * BATCH + bb], 1);
    }
}

// ---------------- host ----------------
extern "C" void kernel_launch(void* const* d_in, const int* in_sizes, int n_in,
                              void* d_out, int out_size) {
    const int*   tok = (const int*)  d_in[0];
    const float* E   = (const float*)d_in[1];
    const float* A   = (const float*)d_in[2];
    const float* U   = (const float*)d_in[3];
    const float* V   = (const float*)d_in[4];
    const float* bv  = (const float*)d_in[5];
    const float* W   = (const float*)d_in[6];
    const float* cv  = (const float*)d_in[7];

    float* y_out = (float*)d_out;                              // [SB][VOCAB]
    float* h_out = (float*)d_out + (size_t)SB * VOCABN;        // [SB][H]

    void *pT0, *pT1, *pAh, *pAl, *pWh, *pWl, *pUh, *pUl, *pXh, *pXl, *pHh, *pHl, *pP;
    cudaGetSymbolAddress(&pT0, g_T0); cudaGetSymbolAddress(&pT1, g_T1);
    cudaGetSymbolAddress(&pAh, g_Ah); cudaGetSymbolAddress(&pAl, g_Al);
    cudaGetSymbolAddress(&pWh, g_Wh); cudaGetSymbolAddress(&pWl, g_Wl);
    cudaGetSymbolAddress(&pUh, g_Uh); cudaGetSymbolAddress(&pUl, g_Ul);
    cudaGetSymbolAddress(&pXh, g_Xh); cudaGetSymbolAddress(&pXl, g_Xl);
    cudaGetSymbolAddress(&pHh, g_Hh); cudaGetSymbolAddress(&pHl, g_Hl);
    cudaGetSymbolAddress(&pP,  g_P);
    float* bufT[2] = { (float*)pT0, (float*)pT1 };

    cudaFuncSetAttribute(gemm_T2, cudaFuncAttributeMaxDynamicSharedMemorySize, SMEM_BYTES);
    cudaFuncSetAttribute(gemm_tn2, cudaFuncAttributeMaxDynamicSharedMemorySize, SMEM_BYTES);

    cudaStream_t s2;
    cudaStreamCreateWithFlags(&s2, cudaStreamNonBlocking);
    cudaEvent_t evG[NCHUNK], evR[NCHUNK];
    for (int c = 0; c < NCHUNK; c++) {
        cudaEventCreateWithFlags(&evG[c], cudaEventDisableTiming);
        cudaEventCreateWithFlags(&evR[c], cudaEventDisableTiming);
    }

    // 1) splits
    {
        int n4 = (HDIM * IDIM * HDIM) / 4;
        split_kernel<<<(n4 + 255) / 256, 256>>>((const float4*)A, (Bf4*)pAh, (Bf4*)pAl, n4);
        n4 = (VOCABN * HDIM) / 4;
        split_kernel<<<(n4 + 255) / 256, 256>>>((const float4*)W, (Bf4*)pWh, (Bf4*)pWl, n4);
        n4 = (HDIM * IDIM) / 4;
        split_kernel<<<(n4 + 255) / 256, 256>>>((const float4*)U, (Bf4*)pUh, (Bf4*)pUl, n4);
    }
    // 2) embedding gather + split
    embed_kernel<<<SB, IDIM>>>(tok, E, (__nv_bfloat16*)pXh, (__nv_bfloat16*)pXl);

    // 3) P = X @ U^T + b
    gemm_tn2<<<dim3(SB / 128, HDIM / 64), 256, SMEM_BYTES>>>(
        (const __nv_bfloat16*)pXh, (const __nv_bfloat16*)pXl,
        (const __nv_bfloat16*)pUh, (const __nv_bfloat16*)pUl,
        bv, (float*)pP, HDIM, IDIM);

    // 4) pipeline: gemm_T(c) on stream 0; fused recur(c) on s2.
    //    WAR guard: gemm_T(c) (writing bufT[c&1]) waits recur(c-2).
    for (int c = 0; c < NCHUNK; c++) {
        if (c >= 2) cudaStreamWaitEvent(0, evR[c - 2], 0);
        gemm_T2<<<dim3(MC / 128, HDIM / 64, HDIM), 256, SMEM_BYTES>>>(V, bufT[c & 1], c);
        cudaEventRecord(evG[c], 0);
        cudaStreamWaitEvent(s2, evG[c], 0);
        zero_cnt_kernel<<<4, 256, 0, s2>>>();
        recur_chunk<<<128, 256, 0, s2>>>(bufT[c & 1], c, h_out,
                                         (__nv_bfloat16*)pHh, (__nv_bfloat16*)pHl);
        cudaEventRecord(evR[c], s2);
    }
    cudaStreamWaitEvent(0, evR[NCHUNK - 1], 0);

    // 5) Y = H @ W^T + c
    gemm_tn2<<<dim3(SB / 128, (VOCABN + 63) / 64), 256, SMEM_BYTES>>>(
        (const __nv_bfloat16*)pHh, (const __nv_bfloat16*)pHl,
        (const __nv_bfloat16*)pWh, (const __nv_bfloat16*)pWl,
        cv, y_out, VOCABN, HDIM);
}

// round 11
// speedup vs baseline: 1.2761x; 1.2761x over previous
#include <cuda_runtime.h>
#include <cuda_bf16.h>

#define SEQ    256
#define BATCH  32
#define IDIM   256
#define HDIM   512
#define VOCABN 10000
#define SB     (SEQ*BATCH)      /* 8192 */
#define CHUNK  32
#define NCHUNK (SEQ/CHUNK)      /* 8 */
#define MC     (CHUNK*BATCH)    /* 1024 */

#define KSTR   72               /* padded smem row stride (bf16 elems), 144B */
#define A_EL   (128*KSTR)
#define B_EL   (64*KSTR)
#define STAGE_EL (2*A_EL + 2*B_EL)
#define SMEM_BYTES (2*STAGE_EL*2)        /* 110592 */

typedef unsigned int u32;

// ---------------- static device scratch ----------------
__device__ float         g_T0[(size_t)MC * HDIM * HDIM];     // 1 GiB, chunk parity 0
__device__ float         g_T1[(size_t)MC * HDIM * HDIM];     // 1 GiB, chunk parity 1
__device__ __nv_bfloat16 g_Ah[(size_t)HDIM * IDIM * HDIM];
__device__ __nv_bfloat16 g_Al[(size_t)HDIM * IDIM * HDIM];
__device__ __nv_bfloat16 g_Wh[(size_t)VOCABN * HDIM];
__device__ __nv_bfloat16 g_Wl[(size_t)VOCABN * HDIM];
__device__ __nv_bfloat16 g_Uh[(size_t)HDIM * IDIM];
__device__ __nv_bfloat16 g_Ul[(size_t)HDIM * IDIM];
__device__ __nv_bfloat16 g_Xh[(size_t)SB * IDIM];
__device__ __nv_bfloat16 g_Xl[(size_t)SB * IDIM];
__device__ __nv_bfloat16 g_Hh[(size_t)SB * HDIM];
__device__ __nv_bfloat16 g_Hl[(size_t)SB * HDIM];
__device__ float         g_P [(size_t)SB * HDIM];

// ---------------- ptx helpers ----------------
__device__ __forceinline__ void mma16816(float c[4], const u32 a[4], const u32 b[2]) {
    asm volatile(
        "mma.sync.aligned.m16n8k16.row.col.f32.bf16.bf16.f32 "
        "{%0,%1,%2,%3}, {%4,%5,%6,%7}, {%8,%9}, {%0,%1,%2,%3};\n"
        : "+f"(c[0]), "+f"(c[1]), "+f"(c[2]), "+f"(c[3])
        : "r"(a[0]), "r"(a[1]), "r"(a[2]), "r"(a[3]), "r"(b[0]), "r"(b[1]));
}
__device__ __forceinline__ u32 smem_u32(const void* p) {
    return (u32)__cvta_generic_to_shared(p);
}
__device__ __forceinline__ void cpa16(u32 dst, const void* src, int sz) {
    asm volatile("cp.async.cg.shared.global [%0], [%1], 16, %2;\n"
                 :: "r"(dst), "l"(src), "r"(sz));
}
__device__ __forceinline__ void cpcommit() { asm volatile("cp.async.commit_group;\n"); }
template<int N> __device__ __forceinline__ void cpwait() {
    asm volatile("cp.async.wait_group %0;\n" :: "n"(N));
}
__device__ __forceinline__ void ldsm4(u32& r0, u32& r1, u32& r2, u32& r3, u32 a) {
    asm volatile("ldmatrix.sync.aligned.m8n8.x4.shared.b16 {%0,%1,%2,%3}, [%4];\n"
                 : "=r"(r0), "=r"(r1), "=r"(r2), "=r"(r3) : "r"(a));
}
__device__ __forceinline__ void ldsm4t(u32& r0, u32& r1, u32& r2, u32& r3, u32 a) {
    asm volatile("ldmatrix.sync.aligned.m8n8.x4.trans.shared.b16 {%0,%1,%2,%3}, [%4];\n"
                 : "=r"(r0), "=r"(r1), "=r"(r2), "=r"(r3) : "r"(a));
}

// ---------------- split / embed ----------------
struct __align__(8) Bf4 { __nv_bfloat16 a, b, c, d; };

__global__ void split_kernel(const float4* __restrict__ src,
                             Bf4* __restrict__ hi, Bf4* __restrict__ lo, int n4) {
    int i = blockIdx.x * blockDim.x + threadIdx.x;
    if (i >= n4) return;
    float4 v = src[i];
    Bf4 h, l;
    h.a = __float2bfloat16(v.x); l.a = __float2bfloat16(v.x - __bfloat162float(h.a));
    h.b = __float2bfloat16(v.y); l.b = __float2bfloat16(v.y - __bfloat162float(h.b));
    h.c = __float2bfloat16(v.z); l.c = __float2bfloat16(v.z - __bfloat162float(h.c));
    h.d = __float2bfloat16(v.w); l.d = __float2bfloat16(v.w - __bfloat162float(h.d));
    hi[i] = h; lo[i] = l;
}

__global__ void embed_kernel(const int* __restrict__ tok, const float* __restrict__ E,
                             __nv_bfloat16* __restrict__ Xh, __nv_bfloat16* __restrict__ Xl) {
    int sb = blockIdx.x;
    int i  = threadIdx.x;
    float v = E[(size_t)tok[sb] * IDIM + i];
    __nv_bfloat16 h = __float2bfloat16(v);
    Xh[(size_t)sb * IDIM + i] = h;
    Xl[(size_t)sb * IDIM + i] = __float2bfloat16(v - __bfloat162float(h));
}

// =======================================================================
// T GEMM (pipelined): T[mloc][j][n] = sum_i X[m][i]*A[j][i*H+n] + V[j][n]
// BM=128 BN=64 BK=64, 2-stage cp.async, ldmatrix(.trans).
// SINGLE CHANGE vs R8: MMA issue order is pass-major (8 independent HMMAs
// between RAW reuses of any accumulator). Per-acc order still hh->hl->lh,
// so accumulation is bit-identical.
// =======================================================================
__global__ __launch_bounds__(256) void gemm_T2(
    const float* __restrict__ Vw, float* __restrict__ T, int chunk)
{
    extern __shared__ __nv_bfloat16 sm[];
    const int tid = threadIdx.x, lane = tid & 31, w = tid >> 5;
    const int grp = lane >> 2, qp2 = (lane & 3) * 2;
    const int wm0 = (w & 3) * 32, wn0 = (w >> 2) * 32;
    const int j = blockIdx.z, mBase = blockIdx.x * 128, nBase = blockIdx.y * 64;
    const int mG = chunk * MC + mBase;

    float acc[2][4][4];
#pragma unroll
    for (int a = 0; a < 2; a++)
#pragma unroll
        for (int b = 0; b < 4; b++)
#pragma unroll
            for (int c = 0; c < 4; c++) acc[a][b][c] = 0.f;

#define PREFETCH_T(kc_) do {                                                   \
    int st_ = (kc_) & 1;                                                       \
    int kB_ = (kc_) * 64;                                                      \
    __nv_bfloat16* Ah_ = sm + st_ * STAGE_EL;                                  \
    __nv_bfloat16* Al_ = Ah_ + A_EL;                                           \
    __nv_bfloat16* Bh_ = Ah_ + 2 * A_EL;                                       \
    __nv_bfloat16* Bl_ = Bh_ + B_EL;                                           \
    _Pragma("unroll")                                                          \
    for (int q = 0; q < 4; q++) {                                              \
        int id = q * 256 + tid;                                                \
        int row = id >> 3, ks = (id & 7) * 8;                                  \
        size_t g = (size_t)(mG + row) * IDIM + kB_ + ks;                       \
        cpa16(smem_u32(Ah_ + row * KSTR + ks), g_Xh + g, 16);                  \
        cpa16(smem_u32(Al_ + row * KSTR + ks), g_Xl + g, 16);                  \
    }                                                                          \
    _Pragma("unroll")                                                          \
    for (int q = 0; q < 2; q++) {                                              \
        int id = q * 256 + tid;                                                \
        int kr = id >> 3, ns = (id & 7) * 8;                                   \
        size_t g = ((size_t)j * IDIM + kB_ + kr) * HDIM + nBase + ns;          \
        cpa16(smem_u32(Bh_ + kr * KSTR + ns), g_Ah + g, 16);                   \
        cpa16(smem_u32(Bl_ + kr * KSTR + ns), g_Al + g, 16);                   \
    } } while (0)

    PREFETCH_T(0); cpcommit();

    const int r8 = lane & 7, kh = (lane >> 3) & 1, nh = lane >> 4;

    for (int kc = 0; kc < 4; kc++) {
        if (kc < 3) { PREFETCH_T(kc + 1); cpcommit(); cpwait<1>(); }
        else        { cpwait<0>(); }
        __syncthreads();
        int st = kc & 1;
        __nv_bfloat16* Ah_ = sm + st * STAGE_EL;
        u32 aAdH = smem_u32(Ah_ + (wm0 + (lane & 15)) * KSTR + (lane >> 4) * 8);
        u32 aAdL = aAdH + A_EL * 2;
        u32 bAdH = smem_u32(Ah_ + 2 * A_EL + (kh * 8 + r8) * KSTR + wn0 + nh * 8);
        u32 bAdL = bAdH + B_EL * 2;
#pragma unroll
        for (int ks = 0; ks < 4; ks++) {
            u32 aH[2][4], aL[2][4], bH[4][2], bL[4][2];
            ldsm4(aH[0][0], aH[0][1], aH[0][2], aH[0][3], aAdH + ks * 32);
            ldsm4(aH[1][0], aH[1][1], aH[1][2], aH[1][3], aAdH + 2304 + ks * 32);
            ldsm4(aL[0][0], aL[0][1], aL[0][2], aL[0][3], aAdL + ks * 32);
            ldsm4(aL[1][0], aL[1][1], aL[1][2], aL[1][3], aAdL + 2304 + ks * 32);
            ldsm4t(bH[0][0], bH[0][1], bH[1][0], bH[1][1], bAdH + ks * 2304);
            ldsm4t(bH[2][0], bH[2][1], bH[3][0], bH[3][1], bAdH + 32 + ks * 2304);
            ldsm4t(bL[0][0], bL[0][1], bL[1][0], bL[1][1], bAdL + ks * 2304);
            ldsm4t(bL[2][0], bL[2][1], bL[3][0], bL[3][1], bAdL + 32 + ks * 2304);
#pragma unroll
            for (int mt = 0; mt < 2; mt++)
#pragma unroll
                for (int nt = 0; nt < 4; nt++)
                    mma16816(acc[mt][nt], aH[mt], bH[nt]);
#pragma unroll
            for (int mt = 0; mt < 2; mt++)
#pragma unroll
                for (int nt = 0; nt < 4; nt++)
                    mma16816(acc[mt][nt], aH[mt], bL[nt]);
#pragma unroll
            for (int mt = 0; mt < 2; mt++)
#pragma unroll
                for (int nt = 0; nt < 4; nt++)
                    mma16816(acc[mt][nt], aL[mt], bH[nt]);
        }
        __syncthreads();
    }
#undef PREFETCH_T

#pragma unroll
    for (int mt = 0; mt < 2; mt++)
#pragma unroll
        for (int nt = 0; nt < 4; nt++) {
            int r  = mBase + wm0 + mt * 16 + grp;
            int cc = nBase + wn0 + nt * 8 + qp2;
            float2 v2 = *(const float2*)&Vw[(size_t)j * HDIM + cc];
            size_t base = ((size_t)r * HDIM + j) * HDIM + cc;
            *(float2*)&T[base] = make_float2(acc[mt][nt][0] + v2.x, acc[mt][nt][1] + v2.y);
            *(float2*)&T[base + (size_t)8 * HDIM * HDIM] =
                make_float2(acc[mt][nt][2] + v2.x, acc[mt][nt][3] + v2.y);
        }
}

// =======================================================================
// TN GEMM (pipelined): C[m][n] = sum_k A[m][k]*B[n][k] + bias[n]
// Same single change: pass-major MMA ordering.
// =======================================================================
__global__ __launch_bounds__(256) void gemm_tn2(
    const __nv_bfloat16* __restrict__ Ahp, const __nv_bfloat16* __restrict__ Alp,
    const __nv_bfloat16* __restrict__ Bhp, const __nv_bfloat16* __restrict__ Blp,
    const float* __restrict__ bias, float* __restrict__ C, int N, int K)
{
    extern __shared__ __nv_bfloat16 sm[];
    const int tid = threadIdx.x, lane = tid & 31, w = tid >> 5;
    const int grp = lane >> 2, qp2 = (lane & 3) * 2;
    const int wm0 = (w & 3) * 32, wn0 = (w >> 2) * 32;
    const int mBase = blockIdx.x * 128, nBase = blockIdx.y * 64;
    const int KC = K >> 6;

    float acc[2][4][4];
#pragma unroll
    for (int a = 0; a < 2; a++)
#pragma unroll
        for (int b = 0; b < 4; b++)
#pragma unroll
            for (int c = 0; c < 4; c++) acc[a][b][c] = 0.f;

#define PREFETCH_N(kc_) do {                                                   \
    int st_ = (kc_) & 1;                                                       \
    int kB_ = (kc_) * 64;                                                      \
    __nv_bfloat16* Ah_ = sm + st_ * STAGE_EL;                                  \
    __nv_bfloat16* Al_ = Ah_ + A_EL;                                           \
    __nv_bfloat16* Bh_ = Ah_ + 2 * A_EL;                                       \
    __nv_bfloat16* Bl_ = Bh_ + B_EL;                                           \
    _Pragma("unroll")                                                          \
    for (int q = 0; q < 4; q++) {                                              \
        int id = q * 256 + tid;                                                \
        int row = id >> 3, ks = (id & 7) * 8;                                  \
        size_t g = (size_t)(mBase + row) * K + kB_ + ks;                       \
        cpa16(smem_u32(Ah_ + row * KSTR + ks), Ahp + g, 16);                   \
        cpa16(smem_u32(Al_ + row * KSTR + ks), Alp + g, 16);                   \
    }                                                                          \
    _Pragma("unroll")                                                          \
    for (int q = 0; q < 2; q++) {                                              \
        int id = q * 256 + tid;                                                \
        int nr = id >> 3, ks = (id & 7) * 8;                                   \
        int gn = nBase + nr;                                                   \
        int ok = gn < N;                                                       \
        int gc = ok ? gn : (N - 1);                                            \
        size_t g = (size_t)gc * K + kB_ + ks;                                  \
        cpa16(smem_u32(Bh_ + nr * KSTR + ks), Bhp + g, ok ? 16 : 0);           \
        cpa16(smem_u32(Bl_ + nr * KSTR + ks), Blp + g, ok ? 16 : 0);           \
    } } while (0)

    PREFETCH_N(0); cpcommit();

    const int r8 = lane & 7, kh = (lane >> 3) & 1, nh = lane >> 4;

    for (int kc = 0; kc < KC; kc++) {
        if (kc < KC - 1) { PREFETCH_N(kc + 1); cpcommit(); cpwait<1>(); }
        else             { cpwait<0>(); }
        __syncthreads();
        int st = kc & 1;
        __nv_bfloat16* Ah_ = sm + st * STAGE_EL;
        u32 aAdH = smem_u32(Ah_ + (wm0 + (lane & 15)) * KSTR + (lane >> 4) * 8);
        u32 aAdL = aAdH + A_EL * 2;
        u32 bAdH = smem_u32(Ah_ + 2 * A_EL + (wn0 + nh * 8 + r8) * KSTR + kh * 8);
        u32 bAdL = bAdH + B_EL * 2;
#pragma unroll
        for (int ks = 0; ks < 4; ks++) {
            u32 aH[2][4], aL[2][4], bH[4][2], bL[4][2];
            ldsm4(aH[0][0], aH[0][1], aH[0][2], aH[0][3], aAdH + ks * 32);
            ldsm4(aH[1][0], aH[1][1], aH[1][2], aH[1][3], aAdH + 2304 + ks * 32);
            ldsm4(aL[0][0], aL[0][1], aL[0][2], aL[0][3], aAdL + ks * 32);
            ldsm4(aL[1][0], aL[1][1], aL[1][2], aL[1][3], aAdL + 2304 + ks * 32);
            ldsm4(bH[0][0], bH[0][1], bH[1][0], bH[1][1], bAdH + ks * 32);
            ldsm4(bH[2][0], bH[2][1], bH[3][0], bH[3][1], bAdH + 2304 + ks * 32);
            ldsm4(bL[0][0], bL[0][1], bL[1][0], bL[1][1], bAdL + ks * 32);
            ldsm4(bL[2][0], bL[2][1], bL[3][0], bL[3][1], bAdL + 2304 + ks * 32);
#pragma unroll
            for (int mt = 0; mt < 2; mt++)
#pragma unroll
                for (int nt = 0; nt < 4; nt++)
                    mma16816(acc[mt][nt], aH[mt], bH[nt]);
#pragma unroll
            for (int mt = 0; mt < 2; mt++)
#pragma unroll
                for (int nt = 0; nt < 4; nt++)
                    mma16816(acc[mt][nt], aH[mt], bL[nt]);
#pragma unroll
            for (int mt = 0; mt < 2; mt++)
#pragma unroll
                for (int nt = 0; nt < 4; nt++)
                    mma16816(acc[mt][nt], aL[mt], bH[nt]);
        }
        __syncthreads();
    }
#undef PREFETCH_N

#pragma unroll
    for (int mt = 0; mt < 2; mt++)
#pragma unroll
        for (int nt = 0; nt < 4; nt++) {
            int r0 = mBase + wm0 + mt * 16 + grp;
            int cc = nBase + wn0 + nt * 8 + qp2;
            if (cc < N) {
                float b0 = bias[cc], b1 = bias[cc + 1];
                *(float2*)&C[(size_t)r0 * N + cc] =
                    make_float2(acc[mt][nt][0] + b0, acc[mt][nt][1] + b1);
                *(float2*)&C[(size_t)(r0 + 8) * N + cc] =
                    make_float2(acc[mt][nt][2] + b0, acc[mt][nt][3] + b1);
            }
        }
}

// ------------- recurrence: h_s = relu( T'[m_s] . h_{s-1} + P[m_s] ) (R6/R8-proven) -------------
__global__ __launch_bounds__(256) void recur_step(
    const float* __restrict__ T, int sLocal, int s,
    float* __restrict__ Hfull,
    __nv_bfloat16* __restrict__ Hh, __nv_bfloat16* __restrict__ Hl)
{
    const int tid = threadIdx.x, lane = tid & 31, w = tid >> 5;
    const int b = blockIdx.x & 31, jt = blockIdx.x >> 5;
    __shared__ float hs[HDIM];
    if (s > 0) {
        const float* hp = Hfull + ((size_t)(s - 1) * BATCH + b) * HDIM;
        for (int k = tid; k < HDIM; k += 256) hs[k] = hp[k];
    }
    __syncthreads();
    const int mloc = sLocal * BATCH + b;
    const int m    = s * BATCH + b;
#pragma unroll
    for (int jj = 0; jj < 2; jj++) {
        int j = jt * 16 + w * 2 + jj;
        float a = 0.f;
        if (s > 0) {
            const float4* row = (const float4*)(T + ((size_t)mloc * HDIM + j) * HDIM);
#pragma unroll
            for (int q = 0; q < 4; q++) {
                float4 v = row[lane + q * 32];
                int k = (lane + q * 32) * 4;
                a += v.x * hs[k] + v.y * hs[k+1] + v.z * hs[k+2] + v.w * hs[k+3];
            }
        }
#pragma unroll
        for (int off = 16; off; off >>= 1) a += __shfl_xor_sync(~0u, a, off);
        if (lane == 0) {
            float pre = a + g_P[(size_t)m * HDIM + j];
            float h = pre > 0.f ? pre : 0.f;
            Hfull[(size_t)m * HDIM + j] = h;
            __nv_bfloat16 hh = __float2bfloat16(h);
            Hh[(size_t)m * HDIM + j] = hh;
            Hl[(size_t)m * HDIM + j] = __float2bfloat16(h - __bfloat162float(hh));
        }
    }
}

// ---------------- host ----------------
extern "C" void kernel_launch(void* const* d_in, const int* in_sizes, int n_in,
                              void* d_out, int out_size) {
    const int*   tok = (const int*)  d_in[0];
    const float* E   = (const float*)d_in[1];
    const float* A   = (const float*)d_in[2];
    const float* U   = (const float*)d_in[3];
    const float* V   = (const float*)d_in[4];
    const float* bv  = (const float*)d_in[5];
    const float* W   = (const float*)d_in[6];
    const float* cv  = (const float*)d_in[7];

    float* y_out = (float*)d_out;                              // [SB][VOCAB]
    float* h_out = (float*)d_out + (size_t)SB * VOCABN;        // [SB][H]

    void *pT0, *pT1, *pAh, *pAl, *pWh, *pWl, *pUh, *pUl, *pXh, *pXl, *pHh, *pHl, *pP;
    cudaGetSymbolAddress(&pT0, g_T0); cudaGetSymbolAddress(&pT1, g_T1);
    cudaGetSymbolAddress(&pAh, g_Ah); cudaGetSymbolAddress(&pAl, g_Al);
    cudaGetSymbolAddress(&pWh, g_Wh); cudaGetSymbolAddress(&pWl, g_Wl);
    cudaGetSymbolAddress(&pUh, g_Uh); cudaGetSymbolAddress(&pUl, g_Ul);
    cudaGetSymbolAddress(&pXh, g_Xh); cudaGetSymbolAddress(&pXl, g_Xl);
    cudaGetSymbolAddress(&pHh, g_Hh); cudaGetSymbolAddress(&pHl, g_Hl);
    cudaGetSymbolAddress(&pP,  g_P);
    float* bufT[2] = { (float*)pT0, (float*)pT1 };

    cudaFuncSetAttribute(gemm_T2, cudaFuncAttributeMaxDynamicSharedMemorySize, SMEM_BYTES);
    cudaFuncSetAttribute(gemm_tn2, cudaFuncAttributeMaxDynamicSharedMemorySize, SMEM_BYTES);

    cudaStream_t s2;
    cudaStreamCreateWithFlags(&s2, cudaStreamNonBlocking);
    cudaEvent_t evG[NCHUNK], evR[NCHUNK];
    for (int c = 0; c < NCHUNK; c++) {
        cudaEventCreateWithFlags(&evG[c], cudaEventDisableTiming);
        cudaEventCreateWithFlags(&evR[c], cudaEventDisableTiming);
    }

    // 1) splits
    {
        int n4 = (HDIM * IDIM * HDIM) / 4;
        split_kernel<<<(n4 + 255) / 256, 256>>>((const float4*)A, (Bf4*)pAh, (Bf4*)pAl, n4);
        n4 = (VOCABN * HDIM) / 4;
        split_kernel<<<(n4 + 255) / 256, 256>>>((const float4*)W, (Bf4*)pWh, (Bf4*)pWl, n4);
        n4 = (HDIM * IDIM) / 4;
        split_kernel<<<(n4 + 255) / 256, 256>>>((const float4*)U, (Bf4*)pUh, (Bf4*)pUl, n4);
    }
    // 2) embedding gather + split
    embed_kernel<<<SB, IDIM>>>(tok, E, (__nv_bfloat16*)pXh, (__nv_bfloat16*)pXl);

    // 3) P = X @ U^T + b
    gemm_tn2<<<dim3(SB / 128, HDIM / 64), 256, SMEM_BYTES>>>(
        (const __nv_bfloat16*)pXh, (const __nv_bfloat16*)pXl,
        (const __nv_bfloat16*)pUh, (const __nv_bfloat16*)pUl,
        bv, (float*)pP, HDIM, IDIM);

    // 4) pipeline: gemm_T(c) on stream 0; per-step recur chain on s2.
    //    WAR guard: gemm_T(c) (writing bufT[c&1]) waits recur(c-2).
    for (int c = 0; c < NCHUNK; c++) {
        if (c >= 2) cudaStreamWaitEvent(0, evR[c - 2], 0);
        gemm_T2<<<dim3(MC / 128, HDIM / 64, HDIM), 256, SMEM_BYTES>>>(V, bufT[c & 1], c);
        cudaEventRecord(evG[c], 0);
        cudaStreamWaitEvent(s2, evG[c], 0);
        for (int t = 0; t < CHUNK; t++) {
            int s = c * CHUNK + t;
            recur_step<<<1024, 256, 0, s2>>>(bufT[c & 1], t, s, h_out,
                                             (__nv_bfloat16*)pHh, (__nv_bfloat16*)pHl);
        }
        cudaEventRecord(evR[c], s2);
    }
    cudaStreamWaitEvent(0, evR[NCHUNK - 1], 0);

    // 5) Y = H @ W^T + c
    gemm_tn2<<<dim3(SB / 128, (VOCABN + 63) / 64), 256, SMEM_BYTES>>>(
        (const __nv_bfloat16*)pHh, (const __nv_bfloat16*)pHl,
        (const __nv_bfloat16*)pWh, (const __nv_bfloat16*)pWl,
        cv, y_out, VOCABN, HDIM);
}

// round 13
// speedup vs baseline: 1.6814x; 1.3176x over previous
#include <cuda_runtime.h>
#include <cuda_fp16.h>

#define SEQ    256
#define BATCH  32
#define IDIM   256
#define HDIM   512
#define VOCABN 10000
#define SB     (SEQ*BATCH)      /* 8192 */
#define CHUNK  32
#define NCHUNK (SEQ/CHUNK)      /* 8 */
#define MC     (CHUNK*BATCH)    /* 1024 */

#define KSTR   72               /* padded smem k-stride (fp16 elems), 144B */
#define A_EL   (128*KSTR)       /* 9216: m-side tile (single fp16)   */
#define B_EL   (64*KSTR)        /* 4608: weight tile (hi or lo)      */
#define STAGE_EL (A_EL + 2*B_EL)        /* 18432 elems */
#define SMEM_BYTES (2*STAGE_EL*2)       /* 73728 B     */

typedef unsigned int u32;

// ---------------- static device scratch ----------------
__device__ float   g_T0[(size_t)MC * HDIM * HDIM];     // 1 GiB, parity 0
__device__ float   g_T1[(size_t)MC * HDIM * HDIM];     // 1 GiB, parity 1
__device__ __half  g_Ah[(size_t)HDIM * IDIM * HDIM];   // A hi (fp16)
__device__ __half  g_Al[(size_t)HDIM * IDIM * HDIM];   // A lo (fp16)
__device__ __half  g_Wh[(size_t)VOCABN * HDIM];
__device__ __half  g_Wl[(size_t)VOCABN * HDIM];
__device__ __half  g_Uh[(size_t)HDIM * IDIM];
__device__ __half  g_Ul[(size_t)HDIM * IDIM];
__device__ __half  g_X [(size_t)SB * IDIM];            // X single fp16
__device__ __half  g_H [(size_t)SB * HDIM];            // H single fp16
__device__ float   g_P [(size_t)SB * HDIM];

// ---------------- ptx helpers ----------------
__device__ __forceinline__ void mmaf16(float c[4], const u32 a[4], const u32 b[2]) {
    asm volatile(
        "mma.sync.aligned.m16n8k16.row.col.f32.f16.f16.f32 "
        "{%0,%1,%2,%3}, {%4,%5,%6,%7}, {%8,%9}, {%0,%1,%2,%3};\n"
        : "+f"(c[0]), "+f"(c[1]), "+f"(c[2]), "+f"(c[3])
        : "r"(a[0]), "r"(a[1]), "r"(a[2]), "r"(a[3]), "r"(b[0]), "r"(b[1]));
}
__device__ __forceinline__ u32 smem_u32(const void* p) {
    return (u32)__cvta_generic_to_shared(p);
}
__device__ __forceinline__ void cpa16(u32 dst, const void* src, int sz) {
    asm volatile("cp.async.cg.shared.global [%0], [%1], 16, %2;\n"
                 :: "r"(dst), "l"(src), "r"(sz));
}
__device__ __forceinline__ void cpcommit() { asm volatile("cp.async.commit_group;\n"); }
template<int N> __device__ __forceinline__ void cpwait() {
    asm volatile("cp.async.wait_group %0;\n" :: "n"(N));
}
__device__ __forceinline__ void ldsm4(u32& r0, u32& r1, u32& r2, u32& r3, u32 a) {
    asm volatile("ldmatrix.sync.aligned.m8n8.x4.shared.b16 {%0,%1,%2,%3}, [%4];\n"
                 : "=r"(r0), "=r"(r1), "=r"(r2), "=r"(r3) : "r"(a));
}
__device__ __forceinline__ void ldsm4t(u32& r0, u32& r1, u32& r2, u32& r3, u32 a) {
    asm volatile("ldmatrix.sync.aligned.m8n8.x4.trans.shared.b16 {%0,%1,%2,%3}, [%4];\n"
                 : "=r"(r0), "=r"(r1), "=r"(r2), "=r"(r3) : "r"(a));
}

// ---------------- split / embed ----------------
struct __align__(8) Hf4 { __half a, b, c, d; };

__global__ void split_kernel(const float4* __restrict__ src,
                             Hf4* __restrict__ hi, Hf4* __restrict__ lo, int n4) {
    int i = blockIdx.x * blockDim.x + threadIdx.x;
    if (i >= n4) return;
    float4 v = src[i];
    Hf4 h, l;
    h.a = __float2half_rn(v.x); l.a = __float2half_rn(v.x - __half2float(h.a));
    h.b = __float2half_rn(v.y); l.b = __float2half_rn(v.y - __half2float(h.b));
    h.c = __float2half_rn(v.z); l.c = __float2half_rn(v.z - __half2float(h.c));
    h.d = __float2half_rn(v.w); l.d = __float2half_rn(v.w - __half2float(h.d));
    hi[i] = h; lo[i] = l;
}

__global__ void embed_kernel(const int* __restrict__ tok, const float* __restrict__ E,
                             __half* __restrict__ X) {
    int sb = blockIdx.x;
    int i  = threadIdx.x;
    X[(size_t)sb * IDIM + i] = __float2half_rn(E[(size_t)tok[sb] * IDIM + i]);
}

// =======================================================================
// T GEMM: T[mloc][j][n] = sum_i X[m][i]*A[j][i*H+n] + V[j][n]
// X single fp16 (m-side), A hi+lo fp16 (2 passes).
// BM=128 BN=64 BK=64, 2-stage cp.async, ldmatrix(.trans).
// grid (MC/128, HDIM/64, HDIM)
// =======================================================================
__global__ __launch_bounds__(256) void gemm_T2(
    const float* __restrict__ Vw, float* __restrict__ T, int chunk)
{
    extern __shared__ __half sm[];
    const int tid = threadIdx.x, lane = tid & 31, w = tid >> 5;
    const int grp = lane >> 2, qp2 = (lane & 3) * 2;
    const int wm0 = (w & 3) * 32, wn0 = (w >> 2) * 32;
    const int j = blockIdx.z, mBase = blockIdx.x * 128, nBase = blockIdx.y * 64;
    const int mG = chunk * MC + mBase;

    float acc[2][4][4];
#pragma unroll
    for (int a = 0; a < 2; a++)
#pragma unroll
        for (int b = 0; b < 4; b++)
#pragma unroll
            for (int c = 0; c < 4; c++) acc[a][b][c] = 0.f;

#define PREFETCH_T(kc_) do {                                                   \
    int st_ = (kc_) & 1;                                                       \
    int kB_ = (kc_) * 64;                                                      \
    __half* Xs_ = sm + st_ * STAGE_EL;                                         \
    __half* Bh_ = Xs_ + A_EL;                                                  \
    __half* Bl_ = Bh_ + B_EL;                                                  \
    _Pragma("unroll")                                                          \
    for (int q = 0; q < 4; q++) {                                              \
        int id = q * 256 + tid;                                                \
        int row = id >> 3, ks = (id & 7) * 8;                                  \
        size_t g = (size_t)(mG + row) * IDIM + kB_ + ks;                       \
        cpa16(smem_u32(Xs_ + row * KSTR + ks), g_X + g, 16);                   \
    }                                                                          \
    _Pragma("unroll")                                                          \
    for (int q = 0; q < 2; q++) {                                              \
        int id = q * 256 + tid;                                                \
        int kr = id >> 3, ns = (id & 7) * 8;                                   \
        size_t g = ((size_t)j * IDIM + kB_ + kr) * HDIM + nBase + ns;          \
        cpa16(smem_u32(Bh_ + kr * KSTR + ns), g_Ah + g, 16);                   \
        cpa16(smem_u32(Bl_ + kr * KSTR + ns), g_Al + g, 16);                   \
    } } while (0)

    PREFETCH_T(0); cpcommit();

    const int r8 = lane & 7, kh = (lane >> 3) & 1, nh = lane >> 4;

    for (int kc = 0; kc < 4; kc++) {
        if (kc < 3) { PREFETCH_T(kc + 1); cpcommit(); cpwait<1>(); }
        else        { cpwait<0>(); }
        __syncthreads();
        int st = kc & 1;
        __half* Xs_ = sm + st * STAGE_EL;
        u32 aAd  = smem_u32(Xs_ + (wm0 + (lane & 15)) * KSTR + (lane >> 4) * 8);
        u32 bAdH = smem_u32(Xs_ + A_EL + (kh * 8 + r8) * KSTR + wn0 + nh * 8);
        u32 bAdL = bAdH + B_EL * 2;
#pragma unroll
        for (int ks = 0; ks < 4; ks++) {
            u32 aF[2][4], bH[4][2], bL[4][2];
            ldsm4(aF[0][0], aF[0][1], aF[0][2], aF[0][3], aAd + ks * 32);
            ldsm4(aF[1][0], aF[1][1], aF[1][2], aF[1][3], aAd + 2304 + ks * 32);
            // trans: ks -> +16 k-rows = +2304B, pair -> +16 n-cols = +32B
            ldsm4t(bH[0][0], bH[0][1], bH[1][0], bH[1][1], bAdH + ks * 2304);
            ldsm4t(bH[2][0], bH[2][1], bH[3][0], bH[3][1], bAdH + 32 + ks * 2304);
            ldsm4t(bL[0][0], bL[0][1], bL[1][0], bL[1][1], bAdL + ks * 2304);
            ldsm4t(bL[2][0], bL[2][1], bL[3][0], bL[3][1], bAdL + 32 + ks * 2304);
#pragma unroll
            for (int mt = 0; mt < 2; mt++)
#pragma unroll
                for (int nt = 0; nt < 4; nt++)
                    mmaf16(acc[mt][nt], aF[mt], bH[nt]);
#pragma unroll
            for (int mt = 0; mt < 2; mt++)
#pragma unroll
                for (int nt = 0; nt < 4; nt++)
                    mmaf16(acc[mt][nt], aF[mt], bL[nt]);
        }
        __syncthreads();
    }
#undef PREFETCH_T

#pragma unroll
    for (int mt = 0; mt < 2; mt++)
#pragma unroll
        for (int nt = 0; nt < 4; nt++) {
            int r  = mBase + wm0 + mt * 16 + grp;
            int cc = nBase + wn0 + nt * 8 + qp2;
            float2 v2 = *(const float2*)&Vw[(size_t)j * HDIM + cc];
            size_t base = ((size_t)r * HDIM + j) * HDIM + cc;
            *(float2*)&T[base] = make_float2(acc[mt][nt][0] + v2.x, acc[mt][nt][1] + v2.y);
            *(float2*)&T[base + (size_t)8 * HDIM * HDIM] =
                make_float2(acc[mt][nt][2] + v2.x, acc[mt][nt][3] + v2.y);
        }
}

// =======================================================================
// TN GEMM: C[m][n] = sum_k A[m][k]*B[n][k] + bias[n]
// A single fp16 [8192][K], B hi+lo fp16 [N][K] (2 passes).
// =======================================================================
__global__ __launch_bounds__(256) void gemm_tn2(
    const __half* __restrict__ Ap,
    const __half* __restrict__ Bhp, const __half* __restrict__ Blp,
    const float* __restrict__ bias, float* __restrict__ C, int N, int K)
{
    extern __shared__ __half sm[];
    const int tid = threadIdx.x, lane = tid & 31, w = tid >> 5;
    const int grp = lane >> 2, qp2 = (lane & 3) * 2;
    const int wm0 = (w & 3) * 32, wn0 = (w >> 2) * 32;
    const int mBase = blockIdx.x * 128, nBase = blockIdx.y * 64;
    const int KC = K >> 6;

    float acc[2][4][4];
#pragma unroll
    for (int a = 0; a < 2; a++)
#pragma unroll
        for (int b = 0; b < 4; b++)
#pragma unroll
            for (int c = 0; c < 4; c++) acc[a][b][c] = 0.f;

#define PREFETCH_N(kc_) do {                                                   \
    int st_ = (kc_) & 1;                                                       \
    int kB_ = (kc_) * 64;                                                      \
    __half* As_ = sm + st_ * STAGE_EL;                                         \
    __half* Bh_ = As_ + A_EL;                                                  \
    __half* Bl_ = Bh_ + B_EL;                                                  \
    _Pragma("unroll")                                                          \
    for (int q = 0; q < 4; q++) {                                              \
        int id = q * 256 + tid;                                                \
        int row = id >> 3, ks = (id & 7) * 8;                                  \
        size_t g = (size_t)(mBase + row) * K + kB_ + ks;                       \
        cpa16(smem_u32(As_ + row * KSTR + ks), Ap + g, 16);                    \
    }                                                                          \
    _Pragma("unroll")                                                          \
    for (int q = 0; q < 2; q++) {                                              \
        int id = q * 256 + tid;                                                \
        int nr = id >> 3, ks = (id & 7) * 8;                                   \
        int gn = nBase + nr;                                                   \
        int ok = gn < N;                                                       \
        int gc = ok ? gn : (N - 1);                                            \
        size_t g = (size_t)gc * K + kB_ + ks;                                  \
        cpa16(smem_u32(Bh_ + nr * KSTR + ks), Bhp + g, ok ? 16 : 0);           \
        cpa16(smem_u32(Bl_ + nr * KSTR + ks), Blp + g, ok ? 16 : 0);           \
    } } while (0)

    PREFETCH_N(0); cpcommit();

    const int r8 = lane & 7, kh = (lane >> 3) & 1, nh = lane >> 4;

    for (int kc = 0; kc < KC; kc++) {
        if (kc < KC - 1) { PREFETCH_N(kc + 1); cpcommit(); cpwait<1>(); }
        else             { cpwait<0>(); }
        __syncthreads();
        int st = kc & 1;
        __half* As_ = sm + st * STAGE_EL;
        u32 aAd  = smem_u32(As_ + (wm0 + (lane & 15)) * KSTR + (lane >> 4) * 8);
        u32 bAdH = smem_u32(As_ + A_EL + (wn0 + nh * 8 + r8) * KSTR + kh * 8);
        u32 bAdL = bAdH + B_EL * 2;
#pragma unroll
        for (int ks = 0; ks < 4; ks++) {
            u32 aF[2][4], bH[4][2], bL[4][2];
            ldsm4(aF[0][0], aF[0][1], aF[0][2], aF[0][3], aAd + ks * 32);
            ldsm4(aF[1][0], aF[1][1], aF[1][2], aF[1][3], aAd + 2304 + ks * 32);
            // plain: ks -> +16 cols = +32B, pair -> +16 n-rows = +2304B
            ldsm4(bH[0][0], bH[0][1], bH[1][0], bH[1][1], bAdH + ks * 32);
            ldsm4(bH[2][0], bH[2][1], bH[3][0], bH[3][1], bAdH + 2304 + ks * 32);
            ldsm4(bL[0][0], bL[0][1], bL[1][0], bL[1][1], bAdL + ks * 32);
            ldsm4(bL[2][0], bL[2][1], bL[3][0], bL[3][1], bAdL + 2304 + ks * 32);
#pragma unroll
            for (int mt = 0; mt < 2; mt++)
#pragma unroll
                for (int nt = 0; nt < 4; nt++)
                    mmaf16(acc[mt][nt], aF[mt], bH[nt]);
#pragma unroll
            for (int mt = 0; mt < 2; mt++)
#pragma unroll
                for (int nt = 0; nt < 4; nt++)
                    mmaf16(acc[mt][nt], aF[mt], bL[nt]);
        }
        __syncthreads();
    }
#undef PREFETCH_N

#pragma unroll
    for (int mt = 0; mt < 2; mt++)
#pragma unroll
        for (int nt = 0; nt < 4; nt++) {
            int r0 = mBase + wm0 + mt * 16 + grp;
            int cc = nBase + wn0 + nt * 8 + qp2;
            if (cc < N) {
                float b0 = bias[cc], b1 = bias[cc + 1];
                *(float2*)&C[(size_t)r0 * N + cc] =
                    make_float2(acc[mt][nt][0] + b0, acc[mt][nt][1] + b1);
                *(float2*)&C[(size_t)(r0 + 8) * N + cc] =
                    make_float2(acc[mt][nt][2] + b0, acc[mt][nt][3] + b1);
            }
        }
}

// ------------- recurrence: h_s = relu( T'[m_s] . h_{s-1} + P[m_s] ) -------------
__global__ __launch_bounds__(256) void recur_step(
    const float* __restrict__ T, int sLocal, int s,
    float* __restrict__ Hfull, __half* __restrict__ Hh)
{
    const int tid = threadIdx.x, lane = tid & 31, w = tid >> 5;
    const int b = blockIdx.x & 31, jt = blockIdx.x >> 5;
    __shared__ float hs[HDIM];
    if (s > 0) {
        const float* hp = Hfull + ((size_t)(s - 1) * BATCH + b) * HDIM;
        for (int k = tid; k < HDIM; k += 256) hs[k] = hp[k];
    }
    __syncthreads();
    const int mloc = sLocal * BATCH + b;
    const int m    = s * BATCH + b;
#pragma unroll
    for (int jj = 0; jj < 2; jj++) {
        int j = jt * 16 + w * 2 + jj;
        float a = 0.f;
        if (s > 0) {
            const float4* row = (const float4*)(T + ((size_t)mloc * HDIM + j) * HDIM);
#pragma unroll
            for (int q = 0; q < 4; q++) {
                float4 v = row[lane + q * 32];
                int k = (lane + q * 32) * 4;
                a += v.x * hs[k] + v.y * hs[k+1] + v.z * hs[k+2] + v.w * hs[k+3];
            }
        }
#pragma unroll
        for (int off = 16; off; off >>= 1) a += __shfl_xor_sync(~0u, a, off);
        if (lane == 0) {
            float pre = a + g_P[(size_t)m * HDIM + j];
            float h = pre > 0.f ? pre : 0.f;
            Hfull[(size_t)m * HDIM + j] = h;
            Hh[(size_t)m * HDIM + j] = __float2half_rn(h);
        }
    }
}

// ---------------- host ----------------
extern "C" void kernel_launch(void* const* d_in, const int* in_sizes, int n_in,
                              void* d_out, int out_size) {
    const int*   tok = (const int*)  d_in[0];
    const float* E   = (const float*)d_in[1];
    const float* A   = (const float*)d_in[2];
    const float* U   = (const float*)d_in[3];
    const float* V   = (const float*)d_in[4];
    const float* bv  = (const float*)d_in[5];
    const float* W   = (const float*)d_in[6];
    const float* cv  = (const float*)d_in[7];

    float* y_out = (float*)d_out;                              // [SB][VOCAB]
    float* h_out = (float*)d_out + (size_t)SB * VOCABN;        // [SB][H]

    void *pT0, *pT1, *pAh, *pAl, *pWh, *pWl, *pUh, *pUl, *pX, *pH, *pP;
    cudaGetSymbolAddress(&pT0, g_T0); cudaGetSymbolAddress(&pT1, g_T1);
    cudaGetSymbolAddress(&pAh, g_Ah); cudaGetSymbolAddress(&pAl, g_Al);
    cudaGetSymbolAddress(&pWh, g_Wh); cudaGetSymbolAddress(&pWl, g_Wl);
    cudaGetSymbolAddress(&pUh, g_Uh); cudaGetSymbolAddress(&pUl, g_Ul);
    cudaGetSymbolAddress(&pX,  g_X);  cudaGetSymbolAddress(&pH,  g_H);
    cudaGetSymbolAddress(&pP,  g_P);
    float* bufT[2] = { (float*)pT0, (float*)pT1 };

    cudaFuncSetAttribute(gemm_T2, cudaFuncAttributeMaxDynamicSharedMemorySize, SMEM_BYTES);
    cudaFuncSetAttribute(gemm_tn2, cudaFuncAttributeMaxDynamicSharedMemorySize, SMEM_BYTES);

    cudaStream_t s2;
    cudaStreamCreateWithFlags(&s2, cudaStreamNonBlocking);
    cudaEvent_t evG[NCHUNK], evR[NCHUNK];
    for (int c = 0; c < NCHUNK; c++) {
        cudaEventCreateWithFlags(&evG[c], cudaEventDisableTiming);
        cudaEventCreateWithFlags(&evR[c], cudaEventDisableTiming);
    }

    // 1) fp16 hi/lo splits of the weight-side operands
    {
        int n4 = (HDIM * IDIM * HDIM) / 4;
        split_kernel<<<(n4 + 255) / 256, 256>>>((const float4*)A, (Hf4*)pAh, (Hf4*)pAl, n4);
        n4 = (VOCABN * HDIM) / 4;
        split_kernel<<<(n4 + 255) / 256, 256>>>((const float4*)W, (Hf4*)pWh, (Hf4*)pWl, n4);
        n4 = (HDIM * IDIM) / 4;
        split_kernel<<<(n4 + 255) / 256, 256>>>((const float4*)U, (Hf4*)pUh, (Hf4*)pUl, n4);
    }
    // 2) embedding gather (single fp16)
    embed_kernel<<<SB, IDIM>>>(tok, E, (__half*)pX);

    // 3) P = X @ U^T + b
    gemm_tn2<<<dim3(SB / 128, HDIM / 64), 256, SMEM_BYTES>>>(
        (const __half*)pX, (const __half*)pUh, (const __half*)pUl,
        bv, (float*)pP, HDIM, IDIM);

    // 4) pipeline: gemm_T(c) on stream 0; per-step recur chain on s2.
    //    WAR guard: gemm_T(c) (writing bufT[c&1]) waits recur(c-2).
    for (int c = 0; c < NCHUNK; c++) {
        if (c >= 2) cudaStreamWaitEvent(0, evR[c - 2], 0);
        gemm_T2<<<dim3(MC / 128, HDIM / 64, HDIM), 256, SMEM_BYTES>>>(V, bufT[c & 1], c);
        cudaEventRecord(evG[c], 0);
        cudaStreamWaitEvent(s2, evG[c], 0);
        for (int t = 0; t < CHUNK; t++) {
            int s = c * CHUNK + t;
            recur_step<<<1024, 256, 0, s2>>>(bufT[c & 1], t, s, h_out, (__half*)pH);
        }
        cudaEventRecord(evR[c], s2);
    }
    cudaStreamWaitEvent(0, evR[NCHUNK - 1], 0);

    // 5) Y = H @ W^T + c
    gemm_tn2<<<dim3(SB / 128, (VOCABN + 63) / 64), 256, SMEM_BYTES>>>(
        (const __half*)pH, (const __half*)pWh, (const __half*)pWl,
        cv, y_out, VOCABN, HDIM);
}

// round 14
// speedup vs baseline: 2.2144x; 1.3170x over previous
#include <cuda_runtime.h>
#include <cuda_fp16.h>

#define SEQ    256
#define BATCH  32
#define IDIM   256
#define HDIM   512
#define VOCABN 10000
#define SB     (SEQ*BATCH)      /* 8192 */
#define CHUNK  32
#define NCHUNK (SEQ/CHUNK)      /* 8 */
#define MC     (CHUNK*BATCH)    /* 1024 */

#define KSTR   72               /* padded smem k-stride (fp16 elems), 144B */
#define A_EL   (128*KSTR)       /* 9216 */
#define B_EL   (64*KSTR)        /* 4608 */

/* gemm_tn2 (P/Y): m-side single + weight hi/lo (2-pass) */
#define N_STAGE_EL (A_EL + 2*B_EL)      /* 18432 */
#define N_SMEM     (2*N_STAGE_EL*2)     /* 73728 */

/* gemm_T2: m-side single + A hi only (1-pass) */
#define T_STAGE_EL (A_EL + B_EL)        /* 13824 */
#define T_SMEM     (2*T_STAGE_EL*2)     /* 55296 */

typedef unsigned int u32;

// ---------------- static device scratch ----------------
__device__ float   g_T0[(size_t)MC * HDIM * HDIM];     // 1 GiB, parity 0
__device__ float   g_T1[(size_t)MC * HDIM * HDIM];     // 1 GiB, parity 1
__device__ __half  g_Ah[(size_t)HDIM * IDIM * HDIM];   // A (single fp16)
__device__ __half  g_Wh[(size_t)VOCABN * HDIM];
__device__ __half  g_Wl[(size_t)VOCABN * HDIM];
__device__ __half  g_Uh[(size_t)HDIM * IDIM];
__device__ __half  g_Ul[(size_t)HDIM * IDIM];
__device__ __half  g_X [(size_t)SB * IDIM];            // X single fp16
__device__ __half  g_H [(size_t)SB * HDIM];            // H single fp16
__device__ float   g_P [(size_t)SB * HDIM];

// ---------------- ptx helpers ----------------
__device__ __forceinline__ void mmaf16(float c[4], const u32 a[4], const u32 b[2]) {
    asm volatile(
        "mma.sync.aligned.m16n8k16.row.col.f32.f16.f16.f32 "
        "{%0,%1,%2,%3}, {%4,%5,%6,%7}, {%8,%9}, {%0,%1,%2,%3};\n"
        : "+f"(c[0]), "+f"(c[1]), "+f"(c[2]), "+f"(c[3])
        : "r"(a[0]), "r"(a[1]), "r"(a[2]), "r"(a[3]), "r"(b[0]), "r"(b[1]));
}
__device__ __forceinline__ u32 smem_u32(const void* p) {
    return (u32)__cvta_generic_to_shared(p);
}
__device__ __forceinline__ void cpa16(u32 dst, const void* src, int sz) {
    asm volatile("cp.async.cg.shared.global [%0], [%1], 16, %2;\n"
                 :: "r"(dst), "l"(src), "r"(sz));
}
__device__ __forceinline__ void cpcommit() { asm volatile("cp.async.commit_group;\n"); }
template<int N> __device__ __forceinline__ void cpwait() {
    asm volatile("cp.async.wait_group %0;\n" :: "n"(N));
}
__device__ __forceinline__ void ldsm4(u32& r0, u32& r1, u32& r2, u32& r3, u32 a) {
    asm volatile("ldmatrix.sync.aligned.m8n8.x4.shared.b16 {%0,%1,%2,%3}, [%4];\n"
                 : "=r"(r0), "=r"(r1), "=r"(r2), "=r"(r3) : "r"(a));
}
__device__ __forceinline__ void ldsm4t(u32& r0, u32& r1, u32& r2, u32& r3, u32 a) {
    asm volatile("ldmatrix.sync.aligned.m8n8.x4.trans.shared.b16 {%0,%1,%2,%3}, [%4];\n"
                 : "=r"(r0), "=r"(r1), "=r"(r2), "=r"(r3) : "r"(a));
}

// ---------------- convert / split / embed ----------------
struct __align__(8) Hf4 { __half a, b, c, d; };

__global__ void cvt_kernel(const float4* __restrict__ src, Hf4* __restrict__ dst, int n4) {
    int i = blockIdx.x * blockDim.x + threadIdx.x;
    if (i >= n4) return;
    float4 v = src[i];
    Hf4 h;
    h.a = __float2half_rn(v.x); h.b = __float2half_rn(v.y);
    h.c = __float2half_rn(v.z); h.d = __float2half_rn(v.w);
    dst[i] = h;
}

__global__ void split_kernel(const float4* __restrict__ src,
                             Hf4* __restrict__ hi, Hf4* __restrict__ lo, int n4) {
    int i = blockIdx.x * blockDim.x + threadIdx.x;
    if (i >= n4) return;
    float4 v = src[i];
    Hf4 h, l;
    h.a = __float2half_rn(v.x); l.a = __float2half_rn(v.x - __half2float(h.a));
    h.b = __float2half_rn(v.y); l.b = __float2half_rn(v.y - __half2float(h.b));
    h.c = __float2half_rn(v.z); l.c = __float2half_rn(v.z - __half2float(h.c));
    h.d = __float2half_rn(v.w); l.d = __float2half_rn(v.w - __half2float(h.d));
    hi[i] = h; lo[i] = l;
}

__global__ void embed_kernel(const int* __restrict__ tok, const float* __restrict__ E,
                             __half* __restrict__ X) {
    int sb = blockIdx.x;
    int i  = threadIdx.x;
    X[(size_t)sb * IDIM + i] = __float2half_rn(E[(size_t)tok[sb] * IDIM + i]);
}

// =======================================================================
// T GEMM (1-pass fp16): T[mloc][j][n] = sum_i X[m][i]*A[j][i*H+n] + V[j][n]
// BM=128 BN=64 BK=64, 2-stage cp.async, ldmatrix(.trans).
// grid (MC/128, HDIM/64, HDIM)
// =======================================================================
__global__ __launch_bounds__(256) void gemm_T2(
    const float* __restrict__ Vw, float* __restrict__ T, int chunk)
{
    extern __shared__ __half sm[];
    const int tid = threadIdx.x, lane = tid & 31, w = tid >> 5;
    const int grp = lane >> 2, qp2 = (lane & 3) * 2;
    const int wm0 = (w & 3) * 32, wn0 = (w >> 2) * 32;
    const int j = blockIdx.z, mBase = blockIdx.x * 128, nBase = blockIdx.y * 64;
    const int mG = chunk * MC + mBase;

    float acc[2][4][4];
#pragma unroll
    for (int a = 0; a < 2; a++)
#pragma unroll
        for (int b = 0; b < 4; b++)
#pragma unroll
            for (int c = 0; c < 4; c++) acc[a][b][c] = 0.f;

#define PREFETCH_T(kc_) do {                                                   \
    int st_ = (kc_) & 1;                                                       \
    int kB_ = (kc_) * 64;                                                      \
    __half* Xs_ = sm + st_ * T_STAGE_EL;                                       \
    __half* Bh_ = Xs_ + A_EL;                                                  \
    _Pragma("unroll")                                                          \
    for (int q = 0; q < 4; q++) {                                              \
        int id = q * 256 + tid;                                                \
        int row = id >> 3, ks = (id & 7) * 8;                                  \
        size_t g = (size_t)(mG + row) * IDIM + kB_ + ks;                       \
        cpa16(smem_u32(Xs_ + row * KSTR + ks), g_X + g, 16);                   \
    }                                                                          \
    _Pragma("unroll")                                                          \
    for (int q = 0; q < 2; q++) {                                              \
        int id = q * 256 + tid;                                                \
        int kr = id >> 3, ns = (id & 7) * 8;                                   \
        size_t g = ((size_t)j * IDIM + kB_ + kr) * HDIM + nBase + ns;          \
        cpa16(smem_u32(Bh_ + kr * KSTR + ns), g_Ah + g, 16);                   \
    } } while (0)

    PREFETCH_T(0); cpcommit();

    const int r8 = lane & 7, kh = (lane >> 3) & 1, nh = lane >> 4;

    for (int kc = 0; kc < 4; kc++) {
        if (kc < 3) { PREFETCH_T(kc + 1); cpcommit(); cpwait<1>(); }
        else        { cpwait<0>(); }
        __syncthreads();
        int st = kc & 1;
        __half* Xs_ = sm + st * T_STAGE_EL;
        u32 aAd  = smem_u32(Xs_ + (wm0 + (lane & 15)) * KSTR + (lane >> 4) * 8);
        u32 bAdH = smem_u32(Xs_ + A_EL + (kh * 8 + r8) * KSTR + wn0 + nh * 8);
#pragma unroll
        for (int ks = 0; ks < 4; ks++) {
            u32 aF[2][4], bH[4][2];
            ldsm4(aF[0][0], aF[0][1], aF[0][2], aF[0][3], aAd + ks * 32);
            ldsm4(aF[1][0], aF[1][1], aF[1][2], aF[1][3], aAd + 2304 + ks * 32);
            // trans: ks -> +16 k-rows = +2304B, pair -> +16 n-cols = +32B
            ldsm4t(bH[0][0], bH[0][1], bH[1][0], bH[1][1], bAdH + ks * 2304);
            ldsm4t(bH[2][0], bH[2][1], bH[3][0], bH[3][1], bAdH + 32 + ks * 2304);
#pragma unroll
            for (int mt = 0; mt < 2; mt++)
#pragma unroll
                for (int nt = 0; nt < 4; nt++)
                    mmaf16(acc[mt][nt], aF[mt], bH[nt]);
        }
        __syncthreads();
    }
#undef PREFETCH_T

#pragma unroll
    for (int mt = 0; mt < 2; mt++)
#pragma unroll
        for (int nt = 0; nt < 4; nt++) {
            int r  = mBase + wm0 + mt * 16 + grp;
            int cc = nBase + wn0 + nt * 8 + qp2;
            float2 v2 = *(const float2*)&Vw[(size_t)j * HDIM + cc];
            size_t base = ((size_t)r * HDIM + j) * HDIM + cc;
            *(float2*)&T[base] = make_float2(acc[mt][nt][0] + v2.x, acc[mt][nt][1] + v2.y);
            *(float2*)&T[base + (size_t)8 * HDIM * HDIM] =
                make_float2(acc[mt][nt][2] + v2.x, acc[mt][nt][3] + v2.y);
        }
}

// =======================================================================
// TN GEMM (2-pass fp16): C[m][n] = sum_k A[m][k]*B[n][k] + bias[n]
// A single fp16 [8192][K], B hi+lo fp16 [N][K].
// =======================================================================
__global__ __launch_bounds__(256) void gemm_tn2(
    const __half* __restrict__ Ap,
    const __half* __restrict__ Bhp, const __half* __restrict__ Blp,
    const float* __restrict__ bias, float* __restrict__ C, int N, int K)
{
    extern __shared__ __half sm[];
    const int tid = threadIdx.x, lane = tid & 31, w = tid >> 5;
    const int grp = lane >> 2, qp2 = (lane & 3) * 2;
    const int wm0 = (w & 3) * 32, wn0 = (w >> 2) * 32;
    const int mBase = blockIdx.x * 128, nBase = blockIdx.y * 64;
    const int KC = K >> 6;

    float acc[2][4][4];
#pragma unroll
    for (int a = 0; a < 2; a++)
#pragma unroll
        for (int b = 0; b < 4; b++)
#pragma unroll
            for (int c = 0; c < 4; c++) acc[a][b][c] = 0.f;

#define PREFETCH_N(kc_) do {                                                   \
    int st_ = (kc_) & 1;                                                       \
    int kB_ = (kc_) * 64;                                                      \
    __half* As_ = sm + st_ * N_STAGE_EL;                                       \
    __half* Bh_ = As_ + A_EL;                                                  \
    __half* Bl_ = Bh_ + B_EL;                                                  \
    _Pragma("unroll")                                                          \
    for (int q = 0; q < 4; q++) {                                              \
        int id = q * 256 + tid;                                                \
        int row = id >> 3, ks = (id & 7) * 8;                                  \
        size_t g = (size_t)(mBase + row) * K + kB_ + ks;                       \
        cpa16(smem_u32(As_ + row * KSTR + ks), Ap + g, 16);                    \
    }                                                                          \
    _Pragma("unroll")                                                          \
    for (int q = 0; q < 2; q++) {                                              \
        int id = q * 256 + tid;                                                \
        int nr = id >> 3, ks = (id & 7) * 8;                                   \
        int gn = nBase + nr;                                                   \
        int ok = gn < N;                                                       \
        int gc = ok ? gn : (N - 1);                                            \
        size_t g = (size_t)gc * K + kB_ + ks;                                  \
        cpa16(smem_u32(Bh_ + nr * KSTR + ks), Bhp + g, ok ? 16 : 0);           \
        cpa16(smem_u32(Bl_ + nr * KSTR + ks), Blp + g, ok ? 16 : 0);           \
    } } while (0)

    PREFETCH_N(0); cpcommit();

    const int r8 = lane & 7, kh = (lane >> 3) & 1, nh = lane >> 4;

    for (int kc = 0; kc < KC; kc++) {
        if (kc < KC - 1) { PREFETCH_N(kc + 1); cpcommit(); cpwait<1>(); }
        else             { cpwait<0>(); }
        __syncthreads();
        int st = kc & 1;
        __half* As_ = sm + st * N_STAGE_EL;
        u32 aAd  = smem_u32(As_ + (wm0 + (lane & 15)) * KSTR + (lane >> 4) * 8);
        u32 bAdH = smem_u32(As_ + A_EL + (wn0 + nh * 8 + r8) * KSTR + kh * 8);
        u32 bAdL = bAdH + B_EL * 2;
#pragma unroll
        for (int ks = 0; ks < 4; ks++) {
            u32 aF[2][4], bH[4][2], bL[4][2];
            ldsm4(aF[0][0], aF[0][1], aF[0][2], aF[0][3], aAd + ks * 32);
            ldsm4(aF[1][0], aF[1][1], aF[1][2], aF[1][3], aAd + 2304 + ks * 32);
            ldsm4(bH[0][0], bH[0][1], bH[1][0], bH[1][1], bAdH + ks * 32);
            ldsm4(bH[2][0], bH[2][1], bH[3][0], bH[3][1], bAdH + 2304 + ks * 32);
            ldsm4(bL[0][0], bL[0][1], bL[1][0], bL[1][1], bAdL + ks * 32);
            ldsm4(bL[2][0], bL[2][1], bL[3][0], bL[3][1], bAdL + 2304 + ks * 32);
#pragma unroll
            for (int mt = 0; mt < 2; mt++)
#pragma unroll
                for (int nt = 0; nt < 4; nt++)
                    mmaf16(acc[mt][nt], aF[mt], bH[nt]);
#pragma unroll
            for (int mt = 0; mt < 2; mt++)
#pragma unroll
                for (int nt = 0; nt < 4; nt++)
                    mmaf16(acc[mt][nt], aF[mt], bL[nt]);
        }
        __syncthreads();
    }
#undef PREFETCH_N

#pragma unroll
    for (int mt = 0; mt < 2; mt++)
#pragma unroll
        for (int nt = 0; nt < 4; nt++) {
            int r0 = mBase + wm0 + mt * 16 + grp;
            int cc = nBase + wn0 + nt * 8 + qp2;
            if (cc < N) {
                float b0 = bias[cc], b1 = bias[cc + 1];
                *(float2*)&C[(size_t)r0 * N + cc] =
                    make_float2(acc[mt][nt][0] + b0, acc[mt][nt][1] + b1);
                *(float2*)&C[(size_t)(r0 + 8) * N + cc] =
                    make_float2(acc[mt][nt][2] + b0, acc[mt][nt][3] + b1);
            }
        }
}

// ------------- recurrence: h_s = relu( T'[m_s] . h_{s-1} + P[m_s] ) -------------
__global__ __launch_bounds__(256) void recur_step(
    const float* __restrict__ T, int sLocal, int s,
    float* __restrict__ Hfull, __half* __restrict__ Hh)
{
    const int tid = threadIdx.x, lane = tid & 31, w = tid >> 5;
    const int b = blockIdx.x & 31, jt = blockIdx.x >> 5;
    __shared__ float hs[HDIM];
    if (s > 0) {
        const float* hp = Hfull + ((size_t)(s - 1) * BATCH + b) * HDIM;
        for (int k = tid; k < HDIM; k += 256) hs[k] = hp[k];
    }
    __syncthreads();
    const int mloc = sLocal * BATCH + b;
    const int m    = s * BATCH + b;
#pragma unroll
    for (int jj = 0; jj < 2; jj++) {
        int j = jt * 16 + w * 2 + jj;
        float a = 0.f;
        if (s > 0) {
            const float4* row = (const float4*)(T + ((size_t)mloc * HDIM + j) * HDIM);
#pragma unroll
            for (int q = 0; q < 4; q++) {
                float4 v = row[lane + q * 32];
                int k = (lane + q * 32) * 4;
                a += v.x * hs[k] + v.y * hs[k+1] + v.z * hs[k+2] + v.w * hs[k+3];
            }
        }
#pragma unroll
        for (int off = 16; off; off >>= 1) a += __shfl_xor_sync(~0u, a, off);
        if (lane == 0) {
            float pre = a + g_P[(size_t)m * HDIM + j];
            float h = pre > 0.f ? pre : 0.f;
            Hfull[(size_t)m * HDIM + j] = h;
            Hh[(size_t)m * HDIM + j] = __float2half_rn(h);
        }
    }
}

// ---------------- host ----------------
extern "C" void kernel_launch(void* const* d_in, const int* in_sizes, int n_in,
                              void* d_out, int out_size) {
    const int*   tok = (const int*)  d_in[0];
    const float* E   = (const float*)d_in[1];
    const float* A   = (const float*)d_in[2];
    const float* U   = (const float*)d_in[3];
    const float* V   = (const float*)d_in[4];
    const float* bv  = (const float*)d_in[5];
    const float* W   = (const float*)d_in[6];
    const float* cv  = (const float*)d_in[7];

    float* y_out = (float*)d_out;                              // [SB][VOCAB]
    float* h_out = (float*)d_out + (size_t)SB * VOCABN;        // [SB][H]

    void *pT0, *pT1, *pAh, *pWh, *pWl, *pUh, *pUl, *pX, *pH, *pP;
    cudaGetSymbolAddress(&pT0, g_T0); cudaGetSymbolAddress(&pT1, g_T1);
    cudaGetSymbolAddress(&pAh, g_Ah);
    cudaGetSymbolAddress(&pWh, g_Wh); cudaGetSymbolAddress(&pWl, g_Wl);
    cudaGetSymbolAddress(&pUh, g_Uh); cudaGetSymbolAddress(&pUl, g_Ul);
    cudaGetSymbolAddress(&pX,  g_X);  cudaGetSymbolAddress(&pH,  g_H);
    cudaGetSymbolAddress(&pP,  g_P);
    float* bufT[2] = { (float*)pT0, (float*)pT1 };

    cudaFuncSetAttribute(gemm_T2, cudaFuncAttributeMaxDynamicSharedMemorySize, T_SMEM);
    cudaFuncSetAttribute(gemm_tn2, cudaFuncAttributeMaxDynamicSharedMemorySize, N_SMEM);

    cudaStream_t s2;
    cudaStreamCreateWithFlags(&s2, cudaStreamNonBlocking);
    cudaEvent_t evG[NCHUNK], evR[NCHUNK];
    for (int c = 0; c < NCHUNK; c++) {
        cudaEventCreateWithFlags(&evG[c], cudaEventDisableTiming);
        cudaEventCreateWithFlags(&evR[c], cudaEventDisableTiming);
    }

    // 1) A -> single fp16; W/U -> fp16 hi/lo splits
    {
        int n4 = (HDIM * IDIM * HDIM) / 4;
        cvt_kernel<<<(n4 + 255) / 256, 256>>>((const float4*)A, (Hf4*)pAh, n4);
        n4 = (VOCABN * HDIM) / 4;
        split_kernel<<<(n4 + 255) / 256, 256>>>((const float4*)W, (Hf4*)pWh, (Hf4*)pWl, n4);
        n4 = (HDIM * IDIM) / 4;
        split_kernel<<<(n4 + 255) / 256, 256>>>((const float4*)U, (Hf4*)pUh, (Hf4*)pUl, n4);
    }
    // 2) embedding gather (single fp16)
    embed_kernel<<<SB, IDIM>>>(tok, E, (__half*)pX);

    // 3) P = X @ U^T + b
    gemm_tn2<<<dim3(SB / 128, HDIM / 64), 256, N_SMEM>>>(
        (const __half*)pX, (const __half*)pUh, (const __half*)pUl,
        bv, (float*)pP, HDIM, IDIM);

    // 4) pipeline: gemm_T(c) on stream 0; per-step recur chain on s2.
    //    WAR guard: gemm_T(c) (writing bufT[c&1]) waits recur(c-2).
    for (int c = 0; c < NCHUNK; c++) {
        if (c >= 2) cudaStreamWaitEvent(0, evR[c - 2], 0);
        gemm_T2<<<dim3(MC / 128, HDIM / 64, HDIM), 256, T_SMEM>>>(V, bufT[c & 1], c);
        cudaEventRecord(evG[c], 0);
        cudaStreamWaitEvent(s2, evG[c], 0);
        for (int t = 0; t < CHUNK; t++) {
            int s = c * CHUNK + t;
            recur_step<<<1024, 256, 0, s2>>>(bufT[c & 1], t, s, h_out, (__half*)pH);
        }
        cudaEventRecord(evR[c], s2);
    }
    cudaStreamWaitEvent(0, evR[NCHUNK - 1], 0);

    // 5) Y = H @ W^T + c
    gemm_tn2<<<dim3(SB / 128, (VOCABN + 63) / 64), 256, N_SMEM>>>(
        (const __half*)pH, (const __half*)pWh, (const __half*)pWl,
        cv, y_out, VOCABN, HDIM);
}